// round 2
// baseline (speedup 1.0000x reference)
#include <cuda_runtime.h>

// DotProductAttention_300647710747
// inp: (B=4, C=80, H=512, W=512) f32, channels = [q(8) | k(8x8) | v(8)]
// out: (B=4, 8, H, W) f32
// Per pixel: qk[v] = sum_k q[k]*k[k][v] / sqrt(8); softmax over v; out = attn*v.
// Pure HBM-streaming: 369 MB traffic, ~50us floor at ~7 TB/s.

#define NK 8
#define NV 8
#define CTOT 80            // NK + NK*NV + NV
#define B_DIM 4
#define HW 262144          // 512*512
#define PLANE4 65536       // HW/4 (float4 elements per channel plane)

__global__ __launch_bounds__(256, 2)
void dpa_kernel(const float4* __restrict__ in, float4* __restrict__ out)
{
    const int t = blockIdx.x * blockDim.x + threadIdx.x;   // 0 .. B*PLANE4-1
    const int b = t >> 16;          // PLANE4 = 2^16
    const int p = t & (PLANE4 - 1);

    const float4* base = in + (size_t)b * CTOT * PLANE4 + p;

    // Load q[8] (channels 0..7)
    float4 q[NK];
#pragma unroll
    for (int i = 0; i < NK; i++)
        q[i] = base[(size_t)i * PLANE4];

    const float scale = 0.3535533905932738f;  // 1/sqrt(8)

    // qk[v] = (sum_k q[k] * K[k][v]) * scale ; K channel = NK + k*NV + v
    float4 acc[NV];
#pragma unroll
    for (int v = 0; v < NV; v++) {
        float4 a = make_float4(0.f, 0.f, 0.f, 0.f);
#pragma unroll
        for (int kk = 0; kk < NK; kk++) {
            float4 kv = base[(size_t)(NK + kk * NV + v) * PLANE4];
            a.x = fmaf(q[kk].x, kv.x, a.x);
            a.y = fmaf(q[kk].y, kv.y, a.y);
            a.z = fmaf(q[kk].z, kv.z, a.z);
            a.w = fmaf(q[kk].w, kv.w, a.w);
        }
        a.x *= scale; a.y *= scale; a.z *= scale; a.w *= scale;
        acc[v] = a;
    }

    // Softmax over v (per lane-component)
    float4 m = acc[0];
#pragma unroll
    for (int v = 1; v < NV; v++) {
        m.x = fmaxf(m.x, acc[v].x);
        m.y = fmaxf(m.y, acc[v].y);
        m.z = fmaxf(m.z, acc[v].z);
        m.w = fmaxf(m.w, acc[v].w);
    }
    float4 s = make_float4(0.f, 0.f, 0.f, 0.f);
#pragma unroll
    for (int v = 0; v < NV; v++) {
        acc[v].x = __expf(acc[v].x - m.x);
        acc[v].y = __expf(acc[v].y - m.y);
        acc[v].z = __expf(acc[v].z - m.z);
        acc[v].w = __expf(acc[v].w - m.w);
        s.x += acc[v].x; s.y += acc[v].y; s.z += acc[v].z; s.w += acc[v].w;
    }
    const float4 rs = make_float4(1.f / s.x, 1.f / s.y, 1.f / s.z, 1.f / s.w);

    // out[b][v] = attn[v] * V[v] ; V channel = 72 + v
    float4* ob = out + (size_t)b * NV * PLANE4 + p;
#pragma unroll
    for (int v = 0; v < NV; v++) {
        float4 vv = base[(size_t)(NK + NK * NV + v) * PLANE4];
        float4 o;
        o.x = acc[v].x * rs.x * vv.x;
        o.y = acc[v].y * rs.y * vv.y;
        o.z = acc[v].z * rs.z * vv.z;
        o.w = acc[v].w * rs.w * vv.w;
        ob[(size_t)v * PLANE4] = o;
    }
}

extern "C" void kernel_launch(void* const* d_in, const int* in_sizes, int n_in,
                              void* d_out, int out_size)
{
    const float4* in4 = (const float4*)d_in[0];
    float4* out4 = (float4*)d_out;
    const int nthreads = B_DIM * PLANE4;   // 262144
    dpa_kernel<<<nthreads / 256, 256>>>(in4, out4);
}